// round 3
// baseline (speedup 1.0000x reference)
#include <cuda_runtime.h>
#include <math.h>

#define E_ 4
#define B_ 8
#define NP_ 96
#define H_ 1024
#define OUT_ 4096
#define NQ_ 144
#define FFH_ 4096

__device__ __constant__ int c_SQ[3] = {64, 48, 32};
__device__ __constant__ int c_L[3]  = {320, 304, 288};
__device__ __constant__ int c_QO[3] = {0, 64, 112};
__device__ __constant__ int c_IO[3] = {0, 256, 512};

// ---------------- scratch (device globals; no allocations allowed) ----------
__device__ float g_gates[B_ * E_];
__device__ float g_x  [NP_ * 64L * H_];
__device__ float g_xn [NP_ * 64L * H_];
__device__ float g_kv0[NP_ * 320L * H_];
__device__ float g_kvn[NP_ * 320L * H_];
__device__ float g_q  [NP_ * 64L * H_];
__device__ float g_k  [NP_ * 320L * H_];
__device__ float g_v  [NP_ * 320L * H_];
__device__ float g_h  [NP_ * 64L * FFH_];
__device__ float g_comb[B_ * (long)NQ_ * OUT_];

__device__ __forceinline__ float* bufptr(int id) {
    switch (id) {
        case 0: return g_x;  case 1: return g_xn; case 2: return g_kv0;
        case 3: return g_kvn; case 4: return g_q; case 5: return g_k;
        case 6: return g_v;  default: return g_h;
    }
}
__device__ __forceinline__ long bufstride(int id) {
    switch (id) {
        case 0: case 1: case 4: return 64L * H_;
        case 7: return 64L * FFH_;
        default: return 320L * H_;
    }
}

// ---------------- block reductions (256 threads) -----------------------------
__device__ __forceinline__ float blockReduceSum(float v, float* sbuf) {
    int t = threadIdx.x;
    for (int o = 16; o; o >>= 1) v += __shfl_down_sync(0xffffffffu, v, o);
    if ((t & 31) == 0) sbuf[t >> 5] = v;
    __syncthreads();
    if (t < 8) {
        v = sbuf[t];
        for (int o = 4; o; o >>= 1) v += __shfl_down_sync(0xffu, v, o);
        if (t == 0) sbuf[0] = v;
    }
    __syncthreads();
    float r = sbuf[0];
    __syncthreads();
    return r;
}
__device__ __forceinline__ float blockReduceMax(float v, float* sbuf) {
    int t = threadIdx.x;
    for (int o = 16; o; o >>= 1) v = fmaxf(v, __shfl_down_sync(0xffffffffu, v, o));
    if ((t & 31) == 0) sbuf[t >> 5] = v;
    __syncthreads();
    if (t < 8) {
        v = sbuf[t];
        for (int o = 4; o; o >>= 1) v = fmaxf(v, __shfl_down_sync(0xffu, v, o));
        if (t == 0) sbuf[0] = v;
    }
    __syncthreads();
    float r = sbuf[0];
    __syncthreads();
    return r;
}

// ---------------- gating -----------------------------------------------------
__global__ void gate_kernel(const float* __restrict__ img,
                            const int* __restrict__ task_ids,
                            const int* __restrict__ elem_ids,
                            const float* __restrict__ task_emb,
                            const float* __restrict__ elem_emb,
                            const float* __restrict__ glw,
                            const float* __restrict__ glb,
                            const float* __restrict__ gw,
                            const float* __restrict__ gb) {
    int b = blockIdx.x;
    int t = threadIdx.x;
    __shared__ float gi[1536];
    __shared__ float sn[1536];
    __shared__ float red[32];
    __shared__ float lg[4];

    float acc0 = 0.f, acc1 = 0.f, acc2 = 0.f, acc3 = 0.f;
    const float* ib = img + (long)b * 576 * H_;
    for (int r = 0; r < 576; r++) {
        const float* row = ib + (long)r * H_;
        acc0 += row[t];        acc1 += row[t + 256];
        acc2 += row[t + 512];  acc3 += row[t + 768];
    }
    const float inv576 = 1.f / 576.f;
    gi[t]       = acc0 * inv576;  gi[t + 256] = acc1 * inv576;
    gi[t + 512] = acc2 * inv576;  gi[t + 768] = acc3 * inv576;
    gi[1024 + t] = task_emb[task_ids[b] * 256 + t];
    gi[1280 + t] = elem_emb[elem_ids[b] * 256 + t];
    __syncthreads();

    float s1 = 0.f;
    for (int d = t; d < 1536; d += 256) s1 += gi[d];
    s1 = blockReduceSum(s1, red);
    float m = s1 / 1536.f;
    float s2 = 0.f;
    for (int d = t; d < 1536; d += 256) { float dd = gi[d] - m; s2 += dd * dd; }
    s2 = blockReduceSum(s2, red);
    float rs = rsqrtf(s2 / 1536.f + 1e-5f);
    for (int d = t; d < 1536; d += 256) sn[d] = (gi[d] - m) * rs * glw[d] + glb[d];
    __syncthreads();

    for (int e = 0; e < 4; e++) {
        float pd = 0.f;
        for (int d = t; d < 1536; d += 256) pd += sn[d] * gw[e * 1536 + d];
        pd = blockReduceSum(pd, red);
        if (t == 0) {
            float l = pd + gb[e];
            lg[e] = fminf(fmaxf(l, -15.f), 15.f);
        }
        __syncthreads();
    }
    if (t == 0) {
        float mx = fmaxf(fmaxf(lg[0], lg[1]), fmaxf(lg[2], lg[3]));
        float pe[4]; float den = 0.f;
        for (int e = 0; e < 4; e++) { pe[e] = expf(lg[e] - mx); den += pe[e]; }
        for (int e = 0; e < 4; e++) pe[e] /= den;
        int i1 = 0;
        for (int e = 1; e < 4; e++) if (pe[e] > pe[i1]) i1 = e;
        int i2 = -1;
        for (int e = 0; e < 4; e++) {
            if (e == i1) continue;
            if (i2 < 0 || pe[e] > pe[i2]) i2 = e;
        }
        float sum2 = pe[i1] + pe[i2] + 1e-9f;
        for (int e = 0; e < 4; e++) g_gates[b * 4 + e] = 0.f;
        g_gates[b * 4 + i1] = pe[i1] / sum2;
        g_gates[b * 4 + i2] = pe[i2] / sum2;
    }
}

// ---------------- build kv0 + init x -----------------------------------------
__global__ void build_kernel(const float* __restrict__ query,
                             const float* __restrict__ img,
                             const float* __restrict__ pp) {
    int p = blockIdx.y;
    int e = p / 24, r = p % 24, b = r / 3, s = r % 3;
    if (g_gates[b * 4 + e] == 0.f) return;
    int tk = blockIdx.x;
    int L = c_L[s];
    if (tk >= L) return;
    int sq = c_SQ[s];
    const float* src;
    if (tk < sq) {
        src = query + ((long)e * NQ_ + c_QO[s] + tk) * H_;
    } else {
        int j = c_IO[s] + tk - sq;
        src = (j < 576) ? img + ((long)b * 576 + j) * H_
                        : pp  + ((long)b * 192 + (j - 576)) * H_;
    }
    float* dst = g_kv0 + (long)p * 320 * H_ + (long)tk * H_;
    int t = threadIdx.x;
    float v0 = src[t], v1 = src[t + 256], v2 = src[t + 512], v3 = src[t + 768];
    dst[t] = v0; dst[t + 256] = v1; dst[t + 512] = v2; dst[t + 768] = v3;
    if (tk < sq) {
        float* xd = g_x + (long)p * 64 * H_ + (long)tk * H_;
        xd[t] = v0; xd[t + 256] = v1; xd[t + 512] = v2; xd[t + 768] = v3;
    }
}

// ---------------- row LayerNorm ----------------------------------------------
__global__ void ln_rows(int src, int dst,
                        const float* __restrict__ wbase,
                        const float* __restrict__ bbase,
                        int m_is_L, int layer) {
    int p = blockIdx.y;
    int e = p / 24, r = p % 24, b = r / 3, s = r % 3;
    if (g_gates[b * 4 + e] == 0.f) return;
    int M = m_is_L ? c_L[s] : c_SQ[s];
    int row = blockIdx.x;
    if (row >= M) return;
    const float* x = bufptr(src) + (long)p * bufstride(src) + (long)row * H_;
    float* y       = bufptr(dst) + (long)p * bufstride(dst) + (long)row * H_;
    const float* w  = wbase + (long)(e * 2 + layer) * H_;
    const float* bb = bbase + (long)(e * 2 + layer) * H_;
    __shared__ float sx[1024];
    __shared__ float red[32];
    int t = threadIdx.x;
    float s1 = 0.f;
    #pragma unroll
    for (int j = 0; j < 4; j++) { float v = x[t + j * 256]; sx[t + j * 256] = v; s1 += v; }
    s1 = blockReduceSum(s1, red);
    float m = s1 / 1024.f;
    float s2 = 0.f;
    #pragma unroll
    for (int j = 0; j < 4; j++) { float d = sx[t + j * 256] - m; s2 += d * d; }
    s2 = blockReduceSum(s2, red);
    float rs = rsqrtf(s2 / 1024.f + 1e-5f);
    #pragma unroll
    for (int j = 0; j < 4; j++) {
        int d = t + j * 256;
        y[d] = (sx[d] - m) * rs * w[d] + bb[d];
    }
}

// ---------------- generic GEMM: C[M,N] = A[M,K] @ W[N,K]^T + bias ------------
// Tile: BM=64, BN=128, BK=16, 128 threads, 8x8 microtile, double-buffered smem.
struct GArgs {
    int a_id; int c_id;
    const float* W;    long w_stride;
    const float* bias; long bias_stride;
    const float* ls;
    int N; int K;
    int m_is_L;
    int epi;     // 0 store, 1 gelu-store, 2 C += ls*(c+bias)
    int layer;
};

#define ASTRIDE 72

__global__ void __launch_bounds__(128) gemm_k(GArgs g) {
    int p = blockIdx.z;
    int e = p / 24, r = p % 24, b = r / 3, s = r % 3;
    if (g_gates[b * 4 + e] == 0.f) return;
    int M = g.m_is_L ? c_L[s] : c_SQ[s];
    int m0 = blockIdx.x * 64;
    if (m0 >= M) return;
    int n0 = blockIdx.y * 128;

    const float* A    = bufptr(g.a_id) + (long)p * bufstride(g.a_id);
    const float* W    = g.W    + (long)(e * 2 + g.layer) * g.w_stride;
    const float* bias = g.bias + (long)(e * 2 + g.layer) * g.bias_stride;
    float* C          = bufptr(g.c_id) + (long)p * bufstride(g.c_id);

    __shared__ float As[2][16][ASTRIDE];
    __shared__ float Ws[2][16][128];

    int tid = threadIdx.x;
    int ty = tid >> 4, tx = tid & 15;         // 8 x 16 thread grid
    int ar = tid & 63, akq = (tid >> 6) << 3; // A loader: row ar, k-offset akq(0/8)

    int am = m0 + ar;
    bool aval = am < M;
    const float* arow = A + (long)am * g.K + akq;
    const float* wrow = W + (long)(n0 + tid) * g.K;

    float acc[8][8];
    #pragma unroll
    for (int i = 0; i < 8; i++)
        #pragma unroll
        for (int j = 0; j < 8; j++) acc[i][j] = 0.f;

    int nc = g.K >> 4;
    float4 ra0, ra1, rw0, rw1, rw2, rw3;

    ra0 = ra1 = make_float4(0.f, 0.f, 0.f, 0.f);
    if (aval) { ra0 = *(const float4*)(arow); ra1 = *(const float4*)(arow + 4); }
    rw0 = *(const float4*)(wrow);      rw1 = *(const float4*)(wrow + 4);
    rw2 = *(const float4*)(wrow + 8);  rw3 = *(const float4*)(wrow + 12);
    {
        As[0][akq + 0][ar] = ra0.x; As[0][akq + 1][ar] = ra0.y;
        As[0][akq + 2][ar] = ra0.z; As[0][akq + 3][ar] = ra0.w;
        As[0][akq + 4][ar] = ra1.x; As[0][akq + 5][ar] = ra1.y;
        As[0][akq + 6][ar] = ra1.z; As[0][akq + 7][ar] = ra1.w;
        Ws[0][ 0][tid] = rw0.x; Ws[0][ 1][tid] = rw0.y; Ws[0][ 2][tid] = rw0.z; Ws[0][ 3][tid] = rw0.w;
        Ws[0][ 4][tid] = rw1.x; Ws[0][ 5][tid] = rw1.y; Ws[0][ 6][tid] = rw1.z; Ws[0][ 7][tid] = rw1.w;
        Ws[0][ 8][tid] = rw2.x; Ws[0][ 9][tid] = rw2.y; Ws[0][10][tid] = rw2.z; Ws[0][11][tid] = rw2.w;
        Ws[0][12][tid] = rw3.x; Ws[0][13][tid] = rw3.y; Ws[0][14][tid] = rw3.z; Ws[0][15][tid] = rw3.w;
    }
    __syncthreads();

    for (int c = 0; c < nc; c++) {
        int cur = c & 1;
        bool have_next = (c + 1 < nc);
        if (have_next) {
            long off = (long)(c + 1) << 4;
            ra0 = ra1 = make_float4(0.f, 0.f, 0.f, 0.f);
            if (aval) { ra0 = *(const float4*)(arow + off); ra1 = *(const float4*)(arow + off + 4); }
            rw0 = *(const float4*)(wrow + off);      rw1 = *(const float4*)(wrow + off + 4);
            rw2 = *(const float4*)(wrow + off + 8);  rw3 = *(const float4*)(wrow + off + 12);
        }
        #pragma unroll
        for (int kk = 0; kk < 16; kk++) {
            float4 av0 = *(const float4*)&As[cur][kk][ty * 8];
            float4 av1 = *(const float4*)&As[cur][kk][ty * 8 + 4];
            float4 wv0 = *(const float4*)&Ws[cur][kk][tx * 8];
            float4 wv1 = *(const float4*)&Ws[cur][kk][tx * 8 + 4];
            float aa[8] = {av0.x, av0.y, av0.z, av0.w, av1.x, av1.y, av1.z, av1.w};
            float ww[8] = {wv0.x, wv0.y, wv0.z, wv0.w, wv1.x, wv1.y, wv1.z, wv1.w};
            #pragma unroll
            for (int i = 0; i < 8; i++)
                #pragma unroll
                for (int j = 0; j < 8; j++)
                    acc[i][j] += aa[i] * ww[j];
        }
        if (have_next) {
            int nb = cur ^ 1;
            As[nb][akq + 0][ar] = ra0.x; As[nb][akq + 1][ar] = ra0.y;
            As[nb][akq + 2][ar] = ra0.z; As[nb][akq + 3][ar] = ra0.w;
            As[nb][akq + 4][ar] = ra1.x; As[nb][akq + 5][ar] = ra1.y;
            As[nb][akq + 6][ar] = ra1.z; As[nb][akq + 7][ar] = ra1.w;
            Ws[nb][ 0][tid] = rw0.x; Ws[nb][ 1][tid] = rw0.y; Ws[nb][ 2][tid] = rw0.z; Ws[nb][ 3][tid] = rw0.w;
            Ws[nb][ 4][tid] = rw1.x; Ws[nb][ 5][tid] = rw1.y; Ws[nb][ 6][tid] = rw1.z; Ws[nb][ 7][tid] = rw1.w;
            Ws[nb][ 8][tid] = rw2.x; Ws[nb][ 9][tid] = rw2.y; Ws[nb][10][tid] = rw2.z; Ws[nb][11][tid] = rw2.w;
            Ws[nb][12][tid] = rw3.x; Ws[nb][13][tid] = rw3.y; Ws[nb][14][tid] = rw3.z; Ws[nb][15][tid] = rw3.w;
        }
        __syncthreads();
    }

    const float* lsp = (g.epi == 2) ? (g.ls + (long)(e * 2 + g.layer) * H_) : nullptr;
    #pragma unroll
    for (int i = 0; i < 8; i++) {
        int m = m0 + ty * 8 + i;
        if (m >= M) continue;
        #pragma unroll
        for (int j = 0; j < 8; j++) {
            int n = n0 + tx * 8 + j;
            float v = acc[i][j] + bias[n];
            long idx = (long)m * g.N + n;
            if (g.epi == 0) {
                C[idx] = v;
            } else if (g.epi == 1) {
                C[idx] = v * 0.5f * (1.f + erff(v * 0.70710678118654752f));
            } else {
                C[idx] += lsp[n] * v;
            }
        }
    }
}

// ---------------- attention (per problem, head, q-row) -----------------------
__global__ void attn_kernel() {
    int p = blockIdx.z;
    int e = p / 24, r = p % 24, b = r / 3, s = r % 3;
    if (g_gates[b * 4 + e] == 0.f) return;
    int sq = c_SQ[s];
    int row = blockIdx.x;
    if (row >= sq) return;
    int L = c_L[s];
    int h = blockIdx.y;
    int t = threadIdx.x;

    __shared__ float sc[320];
    __shared__ float qv[64];
    __shared__ float red[32];
    __shared__ float cbuf[4][64];

    const float* Q = g_q + (long)p * 64 * H_ + (long)row * H_ + h * 64;
    const float* K = g_k + (long)p * 320 * H_ + h * 64;
    const float* V = g_v + (long)p * 320 * H_ + h * 64;

    if (t < 64) qv[t] = Q[t];
    __syncthreads();

    for (int k = t; k < L; k += 256) {
        const float* kr = K + (long)k * H_;
        float d = 0.f;
        #pragma unroll
        for (int dd = 0; dd < 64; dd++) d += qv[dd] * kr[dd];
        sc[k] = d * 0.125f;
    }
    __syncthreads();

    float mx = -1e30f;
    for (int k = t; k < L; k += 256) mx = fmaxf(mx, sc[k]);
    mx = blockReduceMax(mx, red);
    float sum = 0.f;
    for (int k = t; k < L; k += 256) { float ev = expf(sc[k] - mx); sc[k] = ev; sum += ev; }
    sum = blockReduceSum(sum, red);
    float inv = 1.f / sum;

    int d = t & 63, ch = t >> 6;
    float acc = 0.f;
    for (int k = ch; k < L; k += 4) acc += sc[k] * V[(long)k * H_ + d];
    cbuf[ch][d] = acc;
    __syncthreads();
    if (t < 64) {
        float o = (cbuf[0][t] + cbuf[1][t] + cbuf[2][t] + cbuf[3][t]) * inv;
        g_xn[(long)p * 64 * H_ + (long)row * H_ + h * 64 + t] = o;
    }
}

// ---------------- expert-weighted output projection --------------------------
__global__ void __launch_bounds__(128) out_gemm(const float* __restrict__ outp_w,
                                                const float* __restrict__ outp_b) {
    int b = blockIdx.z;
    int m0 = blockIdx.x * 64;
    int n0 = blockIdx.y * 128;

    __shared__ float As[2][16][ASTRIDE];
    __shared__ float Ws[2][16][128];

    int tid = threadIdx.x;
    int ty = tid >> 4, tx = tid & 15;
    int ar = tid & 63, akq = (tid >> 6) << 3;

    int qg = m0 + ar;
    bool aval = qg < NQ_;
    int s = 0, lr = 0;
    if (aval) {
        s = (qg < 64) ? 0 : ((qg < 112) ? 1 : 2);
        lr = qg - c_QO[s];
    }

    float tot[8][8];
    #pragma unroll
    for (int i = 0; i < 8; i++)
        #pragma unroll
        for (int j = 0; j < 8; j++) tot[i][j] = 0.f;

    for (int e = 0; e < 4; e++) {
        float gt = g_gates[b * 4 + e];
        if (gt == 0.f) continue;
        const float* arow = g_x + ((long)(e * 24 + b * 3 + s) * 64 + lr) * H_ + akq;
        const float* wrow = outp_w + (long)e * OUT_ * H_ + (long)(n0 + tid) * H_;

        float acc[8][8];
        #pragma unroll
        for (int i = 0; i < 8; i++)
            #pragma unroll
            for (int j = 0; j < 8; j++) acc[i][j] = 0.f;

        float4 ra0, ra1, rw0, rw1, rw2, rw3;
        ra0 = ra1 = make_float4(0.f, 0.f, 0.f, 0.f);
        if (aval) { ra0 = *(const float4*)(arow); ra1 = *(const float4*)(arow + 4); }
        rw0 = *(const float4*)(wrow);      rw1 = *(const float4*)(wrow + 4);
        rw2 = *(const float4*)(wrow + 8);  rw3 = *(const float4*)(wrow + 12);
        __syncthreads();   // re-sync before refilling buffers for this expert
        As[0][akq + 0][ar] = ra0.x; As[0][akq + 1][ar] = ra0.y;
        As[0][akq + 2][ar] = ra0.z; As[0][akq + 3][ar] = ra0.w;
        As[0][akq + 4][ar] = ra1.x; As[0][akq + 5][ar] = ra1.y;
        As[0][akq + 6][ar] = ra1.z; As[0][akq + 7][ar] = ra1.w;
        Ws[0][ 0][tid] = rw0.x; Ws[0][ 1][tid] = rw0.y; Ws[0][ 2][tid] = rw0.z; Ws[0][ 3][tid] = rw0.w;
        Ws[0][ 4][tid] = rw1.x; Ws[0][ 5][tid] = rw1.y; Ws[0][ 6][tid] = rw1.z; Ws[0][ 7][tid] = rw1.w;
        Ws[0][ 8][tid] = rw2.x; Ws[0][ 9][tid] = rw2.y; Ws[0][10][tid] = rw2.z; Ws[0][11][tid] = rw2.w;
        Ws[0][12][tid] = rw3.x; Ws[0][13][tid] = rw3.y; Ws[0][14][tid] = rw3.z; Ws[0][15][tid] = rw3.w;
        __syncthreads();

        const int nc = H_ >> 4;
        for (int c = 0; c < nc; c++) {
            int cur = c & 1;
            bool have_next = (c + 1 < nc);
            if (have_next) {
                long off = (long)(c + 1) << 4;
                ra0 = ra1 = make_float4(0.f, 0.f, 0.f, 0.f);
                if (aval) { ra0 = *(const float4*)(arow + off); ra1 = *(const float4*)(arow + off + 4); }
                rw0 = *(const float4*)(wrow + off);      rw1 = *(const float4*)(wrow + off + 4);
                rw2 = *(const float4*)(wrow + off + 8);  rw3 = *(const float4*)(wrow + off + 12);
            }
            #pragma unroll
            for (int kk = 0; kk < 16; kk++) {
                float4 av0 = *(const float4*)&As[cur][kk][ty * 8];
                float4 av1 = *(const float4*)&As[cur][kk][ty * 8 + 4];
                float4 wv0 = *(const float4*)&Ws[cur][kk][tx * 8];
                float4 wv1 = *(const float4*)&Ws[cur][kk][tx * 8 + 4];
                float aa[8] = {av0.x, av0.y, av0.z, av0.w, av1.x, av1.y, av1.z, av1.w};
                float ww[8] = {wv0.x, wv0.y, wv0.z, wv0.w, wv1.x, wv1.y, wv1.z, wv1.w};
                #pragma unroll
                for (int i = 0; i < 8; i++)
                    #pragma unroll
                    for (int j = 0; j < 8; j++)
                        acc[i][j] += aa[i] * ww[j];
            }
            if (have_next) {
                int nb = cur ^ 1;
                As[nb][akq + 0][ar] = ra0.x; As[nb][akq + 1][ar] = ra0.y;
                As[nb][akq + 2][ar] = ra0.z; As[nb][akq + 3][ar] = ra0.w;
                As[nb][akq + 4][ar] = ra1.x; As[nb][akq + 5][ar] = ra1.y;
                As[nb][akq + 6][ar] = ra1.z; As[nb][akq + 7][ar] = ra1.w;
                Ws[nb][ 0][tid] = rw0.x; Ws[nb][ 1][tid] = rw0.y; Ws[nb][ 2][tid] = rw0.z; Ws[nb][ 3][tid] = rw0.w;
                Ws[nb][ 4][tid] = rw1.x; Ws[nb][ 5][tid] = rw1.y; Ws[nb][ 6][tid] = rw1.z; Ws[nb][ 7][tid] = rw1.w;
                Ws[nb][ 8][tid] = rw2.x; Ws[nb][ 9][tid] = rw2.y; Ws[nb][10][tid] = rw2.z; Ws[nb][11][tid] = rw2.w;
                Ws[nb][12][tid] = rw3.x; Ws[nb][13][tid] = rw3.y; Ws[nb][14][tid] = rw3.z; Ws[nb][15][tid] = rw3.w;
            }
            __syncthreads();
        }

        const float* bias = outp_b + (long)e * OUT_;
        #pragma unroll
        for (int i = 0; i < 8; i++)
            #pragma unroll
            for (int j = 0; j < 8; j++)
                tot[i][j] += gt * (acc[i][j] + bias[n0 + tx * 8 + j]);
    }

    #pragma unroll
    for (int i = 0; i < 8; i++) {
        int m = m0 + ty * 8 + i;
        if (m >= NQ_) continue;
        #pragma unroll
        for (int j = 0; j < 8; j++) {
            int n = n0 + tx * 8 + j;
            g_comb[((long)b * NQ_ + m) * OUT_ + n] = tot[i][j];
        }
    }
}

// ---------------- final RMS + scaling ----------------------------------------
__global__ void rms_kernel(const float* __restrict__ final_w,
                           const float* __restrict__ out_gain,
                           float* __restrict__ out) {
    int q = blockIdx.x, b = blockIdx.y;
    int t = threadIdx.x;
    const float* c = g_comb + ((long)b * NQ_ + q) * OUT_;
    float s2 = 0.f;
    for (int o = t; o < OUT_; o += 256) { float v = c[o]; s2 += v * v; }
    __shared__ float red[32];
    s2 = blockReduceSum(s2, red);
    float rs = rsqrtf(s2 / (float)OUT_ + 1e-6f);
    float* orow = out + ((long)b * NQ_ + q) * OUT_;
    for (int o = t; o < OUT_; o += 256) orow[o] = c[o] * rs * final_w[o] * out_gain[o];
}

// ---------------- host driver ------------------------------------------------
extern "C" void kernel_launch(void* const* d_in, const int* in_sizes, int n_in,
                              void* d_out, int out_size) {
    const float* image_embs = (const float*)d_in[0];
    const float* phys       = (const float*)d_in[1];
    const int*   task_ids   = (const int*)d_in[2];
    const int*   elem_ids   = (const int*)d_in[3];
    const float* query      = (const float*)d_in[4];
    const float* ln1_w      = (const float*)d_in[5];
    const float* ln1_b      = (const float*)d_in[6];
    const float* ln1kv_w    = (const float*)d_in[7];
    const float* ln1kv_b    = (const float*)d_in[8];
    const float* attn_in_w  = (const float*)d_in[9];
    const float* attn_in_b  = (const float*)d_in[10];
    const float* attn_out_w = (const float*)d_in[11];
    const float* attn_out_b = (const float*)d_in[12];
    const float* ls1        = (const float*)d_in[13];
    const float* ls2        = (const float*)d_in[14];
    const float* ln2_w      = (const float*)d_in[15];
    const float* ln2_b      = (const float*)d_in[16];
    const float* fc_w       = (const float*)d_in[17];
    const float* fc_b       = (const float*)d_in[18];
    const float* proj_w     = (const float*)d_in[19];
    const float* proj_b     = (const float*)d_in[20];
    const float* outp_w     = (const float*)d_in[21];
    const float* outp_b     = (const float*)d_in[22];
    const float* task_emb   = (const float*)d_in[23];
    const float* elem_emb   = (const float*)d_in[24];
    const float* gate_ln_w  = (const float*)d_in[25];
    const float* gate_ln_b  = (const float*)d_in[26];
    const float* gate_w     = (const float*)d_in[27];
    const float* gate_b     = (const float*)d_in[28];
    const float* output_gain= (const float*)d_in[29];
    const float* final_w    = (const float*)d_in[30];
    (void)in_sizes; (void)n_in; (void)out_size;

    gate_kernel<<<B_, 256>>>(image_embs, task_ids, elem_ids, task_emb, elem_emb,
                             gate_ln_w, gate_ln_b, gate_w, gate_b);
    build_kernel<<<dim3(320, NP_), 256>>>(query, image_embs, phys);

    for (int l = 0; l < 2; l++) {
        ln_rows<<<dim3(320, NP_), 256>>>(2, 3, ln1kv_w, ln1kv_b, 1, l);
        ln_rows<<<dim3(64, NP_), 256>>>(0, 1, ln1_w, ln1_b, 0, l);

        GArgs gq = {};
        gq.a_id = 1; gq.c_id = 4;
        gq.W = attn_in_w; gq.w_stride = 3072L * 1024;
        gq.bias = attn_in_b; gq.bias_stride = 3072;
        gq.ls = nullptr; gq.N = 1024; gq.K = 1024;
        gq.m_is_L = 0; gq.epi = 0; gq.layer = l;
        gemm_k<<<dim3(1, 8, NP_), 128>>>(gq);

        GArgs gk = gq;
        gk.a_id = 3; gk.c_id = 5;
        gk.W = attn_in_w + 1024L * 1024; gk.bias = attn_in_b + 1024;
        gk.m_is_L = 1;
        gemm_k<<<dim3(5, 8, NP_), 128>>>(gk);

        GArgs gv = gk;
        gv.c_id = 6;
        gv.W = attn_in_w + 2048L * 1024; gv.bias = attn_in_b + 2048;
        gemm_k<<<dim3(5, 8, NP_), 128>>>(gv);

        attn_kernel<<<dim3(64, 16, NP_), 256>>>();

        GArgs go = {};
        go.a_id = 1; go.c_id = 0;
        go.W = attn_out_w; go.w_stride = 1024L * 1024;
        go.bias = attn_out_b; go.bias_stride = 1024;
        go.ls = ls1; go.N = 1024; go.K = 1024;
        go.m_is_L = 0; go.epi = 2; go.layer = l;
        gemm_k<<<dim3(1, 8, NP_), 128>>>(go);

        ln_rows<<<dim3(64, NP_), 256>>>(0, 1, ln2_w, ln2_b, 0, l);

        GArgs gf = {};
        gf.a_id = 1; gf.c_id = 7;
        gf.W = fc_w; gf.w_stride = 4096L * 1024;
        gf.bias = fc_b; gf.bias_stride = 4096;
        gf.ls = nullptr; gf.N = 4096; gf.K = 1024;
        gf.m_is_L = 0; gf.epi = 1; gf.layer = l;
        gemm_k<<<dim3(1, 32, NP_), 128>>>(gf);

        GArgs gp = {};
        gp.a_id = 7; gp.c_id = 0;
        gp.W = proj_w; gp.w_stride = 1024L * 4096;
        gp.bias = proj_b; gp.bias_stride = 1024;
        gp.ls = ls2; gp.N = 1024; gp.K = 4096;
        gp.m_is_L = 0; gp.epi = 2; gp.layer = l;
        gemm_k<<<dim3(1, 8, NP_), 128>>>(gp);
    }

    out_gemm<<<dim3(3, 32, B_), 128>>>(outp_w, outp_b);
    rms_kernel<<<dim3(NQ_, B_), 256>>>(final_w, output_gain, (float*)d_out);
}